// round 16
// baseline (speedup 1.0000x reference)
#include <cuda_runtime.h>
#include <cuda_fp16.h>
#include <cstdint>

#define BB   16
#define LL   512
#define CC   256
#define MEL  4096

typedef unsigned long long ull;

// ---------------------------------------------------------------------------
// Scratch (__device__ globals — allocations are forbidden)
// ---------------------------------------------------------------------------
__device__ uint32_t g_xpk[BB * LL * 128];         // x packed half2 [b][l][kpair]
__device__ uint32_t g_h1pk[BB * LL * 128];        // h1 packed half2
__device__ int      g_idx[BB * MEL];              // per-frame token index
__device__ uint32_t g_wpk[2 * 3 * 128 * 256];     // weights packed half2 [conv][tap][kpair][n]

// ---------------------------------------------------------------------------
__device__ __forceinline__ uint32_t pack_h2(float a, float b) {
    __half2 h = __floats2half2_rn(a, b);
    return *reinterpret_cast<uint32_t*>(&h);
}
__device__ __forceinline__ void mma_f16(float* d, const uint32_t* a, const uint32_t* b) {
    asm volatile(
        "mma.sync.aligned.m16n8k16.row.col.f32.f16.f16.f32 "
        "{%0,%1,%2,%3}, {%4,%5,%6,%7}, {%8,%9}, {%0,%1,%2,%3};"
        : "+f"(d[0]), "+f"(d[1]), "+f"(d[2]), "+f"(d[3])
        : "r"(a[0]), "r"(a[1]), "r"(a[2]), "r"(a[3]), "r"(b[0]), "r"(b[1]));
}
__device__ __forceinline__ uint32_t smem_u32(const void* p) {
    uint32_t a;
    asm("{ .reg .u64 t; cvta.to.shared.u64 t, %1; cvt.u32.u64 %0, t; }"
        : "=r"(a) : "l"(p));
    return a;
}
#define CP_ASYNC16(dst, src) \
    asm volatile("cp.async.ca.shared.global [%0], [%1], 16;" :: "r"(dst), "l"(src))
#define CP_COMMIT() asm volatile("cp.async.commit_group;" ::: "memory")
#define CP_WAIT2()  asm volatile("cp.async.wait_group 2;" ::: "memory")
#define CP_WAIT1()  asm volatile("cp.async.wait_group 1;" ::: "memory")
#define CP_WAIT0()  asm volatile("cp.async.wait_group 0;" ::: "memory")

// smem geometry (uint32 units). M=32 tile: A = 34 rows.
#define A_STR 132
#define B_STR 264
#define A_U32 (34 * A_STR)               // 4488
#define B16_U32 (16 * B_STR)             // 4224 (one 16-kpair chunk)
#define IDX_OFF (A_U32 + 4 * B16_U32)    // 21384
#define SMEM_BYTES ((IDX_OFF + 128) * 4) // 86048  -> 2 CTAs/SM

// ---------------------------------------------------------------------------
// Prep (R11 form): x pack (0..255), w pack (256..303), cumsum/idx (304..319)
// ---------------------------------------------------------------------------
__global__ void __launch_bounds__(512) prep_kernel(const float* __restrict__ x,
                                                   const float* __restrict__ w1,
                                                   const float* __restrict__ w2,
                                                   const int* __restrict__ dur)
{
    if (blockIdx.x < 256) {
        int j = blockIdx.x * 512 + threadIdx.x;        // slots j, j+131072
        int j2 = j + 131072;
        const float* s0 = x + (size_t)(j >> 5) * CC + (j & 31) * 8;
        const float* s1 = x + (size_t)(j2 >> 5) * CC + (j2 & 31) * 8;
        float4 a0 = *(const float4*)(s0);
        float4 b0 = *(const float4*)(s0 + 4);
        float4 a1 = *(const float4*)(s1);
        float4 b1 = *(const float4*)(s1 + 4);
        uint4 o0, o1;
        o0.x = pack_h2(a0.x, a0.y); o0.y = pack_h2(a0.z, a0.w);
        o0.z = pack_h2(b0.x, b0.y); o0.w = pack_h2(b0.z, b0.w);
        o1.x = pack_h2(a1.x, a1.y); o1.y = pack_h2(a1.z, a1.w);
        o1.z = pack_h2(b1.x, b1.y); o1.w = pack_h2(b1.z, b1.w);
        ((uint4*)g_xpk)[j]  = o0;
        ((uint4*)g_xpk)[j2] = o1;
        return;
    }
    if (blockIdx.x < 304) {
        int idx = (blockIdx.x - 256) * 512 + threadIdx.x;  // 0..24575; +24576
#pragma unroll
        for (int r = 0; r < 2; r++) {
            int id = idx + r * 24576;
            int n4 = id & 63;
            int kp = (id >> 6) & 127;
            int t  = id >> 13;                         // 0..5
            int tap = t % 3, conv = t / 3;
            const float* src = (conv ? w2 : w1) + (size_t)tap * 65536
                             + (size_t)(2 * kp) * 256 + n4 * 4;
            float4 lo = *(const float4*)(src);
            float4 hi = *(const float4*)(src + 256);
            uint4 o;
            o.x = pack_h2(lo.x, hi.x);
            o.y = pack_h2(lo.y, hi.y);
            o.z = pack_h2(lo.z, hi.z);
            o.w = pack_h2(lo.w, hi.w);
            *(uint4*)(g_wpk + ((size_t)(conv * 3 + tap) * 128 + kp) * 256 + n4 * 4) = o;
        }
        return;
    }
    // cumsum + frame->token idx, warp-shuffle scan
    __shared__ int s[LL];
    __shared__ int wsum[16];
    int b = blockIdx.x - 304, tid = threadIdx.x;
    int lane = tid & 31, wid = tid >> 5;
    int v = dur[b * LL + tid];
#pragma unroll
    for (int off = 1; off < 32; off <<= 1) {
        int t = __shfl_up_sync(0xffffffffu, v, off);
        if (lane >= off) v += t;
    }
    if (lane == 31) wsum[wid] = v;
    __syncthreads();
    if (wid == 0 && lane < 16) {
        int w = wsum[lane];
#pragma unroll
        for (int off = 1; off < 16; off <<= 1) {
            int t = __shfl_up_sync(0xffffu, w, off);
            if (lane >= off) w += t;
        }
        wsum[lane] = w;
    }
    __syncthreads();
    if (wid > 0) v += wsum[wid - 1];
    s[tid] = v;
    __syncthreads();
    int total = s[LL - 1];
#pragma unroll
    for (int r = 0; r < 8; r++) {
        int t = tid + r * 512;
        int lo = 0, hi = LL;
        while (lo < hi) {
            int mid = (lo + hi) >> 1;
            if (s[mid] <= t) lo = mid + 1; else hi = mid;
        }
        g_idx[b * MEL + t] = (t < total) ? min(lo, LL - 1) : -1;
    }
}

// ---------------------------------------------------------------------------
// Fused conv1d(K=3,SAME)+bias+ReLU+LN [+linear head if FINAL], fp16 MMA.
// CTA = [32 l x 256 f], 256 threads / 8 warps, warp tile 32x32, 2 CTAs/SM.
// A via cp.async (packed); B in a 4-buffer, 16-kpair, 24-iter pipeline.
// Each conv streams half the regulate frames (128/CTA), gathers before MMA.
// ---------------------------------------------------------------------------
template <bool FINAL>
__global__ void __launch_bounds__(256, 2)
conv_mma_kernel(const float* __restrict__ xin,
                const float* __restrict__ bias,
                const float* __restrict__ gamma,
                const float* __restrict__ beta,
                const float* __restrict__ linw,
                const float* __restrict__ linb,
                float* __restrict__ predout,
                float* __restrict__ regout)
{
    extern __shared__ __align__(16) uint32_t smu[];
    uint32_t* sA2 = smu;
    int* sIdx = (int*)(smu + IDX_OFF);
    const uint32_t sa_u32 = smem_u32(sA2);
    const uint32_t sb_base = sa_u32 + A_U32 * 4;
    const uint32_t sidx_u32 = smem_u32(sIdx);

    const int tid  = threadIdx.x;
    const int warp = tid >> 5, lane = tid & 31;
    const int g = lane >> 2, q = lane & 3;
    const int n0 = warp * 32;
    const int b  = blockIdx.y;
    const int t  = blockIdx.x;
    const int l0 = t * 32;
    const int CONV = FINAL ? 1 : 0;
    const int fbase = t * 128 + (FINAL ? 2048 : 0);

    // stage one 16-kpair chunk ck (0..23) into buffer ck&3
    auto stageB = [&](int ck) {
        const int buf = ck & 3;
        const uint32_t* src = g_wpk + ((size_t)(CONV * 3 + (ck >> 3)) * 128 + (ck & 7) * 16) * 256;
        const uint32_t bdst = sb_base + (uint32_t)buf * B16_U32 * 4;
#pragma unroll
        for (int i = 0; i < 4; i++) {
            int idx = tid + i * 256;               // 0..1023 16B segs
            int c = idx >> 6, n4 = idx & 63;
            CP_ASYNC16(bdst + (uint32_t)(c * B_STR + n4 * 4) * 4,
                       src + (size_t)c * 256 + n4 * 4);
        }
        CP_COMMIT();
    };

    stageB(0);                                      // g0
    // ---- A (packed fp16) + idx slice, one commit group (g1) ----
    {
        const uint32_t* apk = (FINAL ? g_h1pk : g_xpk) + (size_t)b * LL * 128;
#pragma unroll
        for (int i = 0; i < 5; i++) {
            int idx = tid + i * 256;               // need 34*32 = 1088 segs
            if (idx < 34 * 32) {
                int row = idx >> 5, seg = idx & 31;
                int grow = l0 + row - 1;
                if (grow >= 0 && grow < LL)
                    CP_ASYNC16(sa_u32 + (uint32_t)(row * A_STR + seg * 4) * 4,
                               apk + (size_t)grow * 128 + seg * 4);
                else
                    *(float4*)(sA2 + row * A_STR + seg * 4) =
                        make_float4(0.f, 0.f, 0.f, 0.f);
            }
        }
        if (tid < 32)
            CP_ASYNC16(sidx_u32 + tid * 16, g_idx + b * MEL + fbase + tid * 4);
        CP_COMMIT();
    }
    stageB(1);                                      // g2
    stageB(2);                                      // g3

    float acc[2][4][4];
#pragma unroll
    for (int mt = 0; mt < 2; mt++)
#pragma unroll
        for (int nt = 0; nt < 4; nt++)
#pragma unroll
            for (int r = 0; r < 4; r++) acc[mt][nt][r] = 0.f;

    for (int it = 0; it < 24; it++) {
        const int ktap = it >> 3, koff = (it & 7) * 16;
        if (it <= 21) CP_WAIT2();
        else if (it == 22) CP_WAIT1();
        else CP_WAIT0();
        __syncthreads();
        if (it + 3 < 24) stageB(it + 3);

        // ---- regulate: issue gathers now; latency hides under MMA ----
        int ix[2];
        float4 vv[2];
#pragma unroll
        for (int u = 0; u < 2; u++) {
            int s = it * 2 + u;
            ix[u] = (s < 32) ? sIdx[(tid + s * 256) >> 6] : -1;
        }
#pragma unroll
        for (int u = 0; u < 2; u++) {
            vv[u] = make_float4(0.f, 0.f, 0.f, 0.f);
            if (ix[u] >= 0) {
                int s = it * 2 + u;
                int c4 = (tid + s * 256) & 63;
                vv[u] = *(const float4*)(xin + ((size_t)b * LL + ix[u]) * CC + c4 * 4);
            }
        }

        const uint32_t* ab = sA2 + (ktap + g) * A_STR + koff + q;
        const uint32_t* bb = (uint32_t*)(smu + A_U32 + (it & 3) * B16_U32) + n0 + g;
#pragma unroll
        for (int ks = 0; ks < 2; ks++) {
            uint32_t af[2][4], bf[4][2];
#pragma unroll
            for (int mt = 0; mt < 2; mt++) {
                const uint32_t* ap = ab + mt * (16 * A_STR) + ks * 8;
                af[mt][0] = ap[0];
                af[mt][1] = ap[8 * A_STR];
                af[mt][2] = ap[4];
                af[mt][3] = ap[8 * A_STR + 4];
            }
#pragma unroll
            for (int nt = 0; nt < 4; nt++) {
                bf[nt][0] = bb[(ks * 8 + q) * B_STR + nt * 8];
                bf[nt][1] = bb[(ks * 8 + q + 4) * B_STR + nt * 8];
            }
#pragma unroll
            for (int mt = 0; mt < 2; mt++)
#pragma unroll
                for (int nt = 0; nt < 4; nt++)
                    mma_f16(acc[mt][nt], af[mt], bf[nt]);
        }

        // ---- regulate stores ----
#pragma unroll
        for (int u = 0; u < 2; u++) {
            int s = it * 2 + u;
            if (s < 32) {
                int j = tid + s * 256;
                int fr = j >> 6, c4 = j & 63;
                *(float4*)(regout + ((size_t)b * MEL + fbase + fr) * CC + c4 * 4) = vv[u];
            }
        }
    }
    __syncthreads();

    // ---- epilogue: bias + ReLU + LN (fused), optional linear head ----
    float bi[8], ga[8], be[8], lw[8];
#pragma unroll
    for (int nt = 0; nt < 4; nt++)
#pragma unroll
        for (int j = 0; j < 2; j++) {
            int c = n0 + nt * 8 + 2 * q + j;
            bi[nt * 2 + j] = __ldg(bias + c);
            ga[nt * 2 + j] = __ldg(gamma + c);
            be[nt * 2 + j] = __ldg(beta + c);
            if (FINAL) lw[nt * 2 + j] = __ldg(linw + c);
        }

    float v[2][2][8];
    float2* red   = (float2*)sA2;                  // [32 rows][8 warps]
    float2* stats = red + 256;                     // [32]
    float*  dred  = (float*)sA2 + 1024;            // [32 rows][8 warps]

#pragma unroll
    for (int mt = 0; mt < 2; mt++)
#pragma unroll
        for (int h = 0; h < 2; h++) {
            float s = 0.f, s2 = 0.f;
#pragma unroll
            for (int nt = 0; nt < 4; nt++)
#pragma unroll
                for (int j = 0; j < 2; j++) {
                    float x = acc[mt][nt][h * 2 + j] + bi[nt * 2 + j];
                    x = fmaxf(x, 0.f);
                    v[mt][h][nt * 2 + j] = x;
                    s += x; s2 += x * x;
                }
            s  += __shfl_xor_sync(0xffffffffu, s, 1);
            s2 += __shfl_xor_sync(0xffffffffu, s2, 1);
            s  += __shfl_xor_sync(0xffffffffu, s, 2);
            s2 += __shfl_xor_sync(0xffffffffu, s2, 2);
            if (q == 0)
                red[(mt * 16 + g + 8 * h) * 8 + warp] = make_float2(s, s2);
        }
    __syncthreads();
    if (tid < 32) {
        float s = 0.f, s2 = 0.f;
#pragma unroll
        for (int wv = 0; wv < 8; wv++) {
            float2 p = red[tid * 8 + wv];
            s += p.x; s2 += p.y;
        }
        float mu = s * (1.f / 256.f);
        float var = s2 * (1.f / 256.f) - mu * mu;
        stats[tid] = make_float2(mu, rsqrtf(var + 1e-5f));
    }
    __syncthreads();

    if (!FINAL) {
#pragma unroll
        for (int mt = 0; mt < 2; mt++)
#pragma unroll
            for (int h = 0; h < 2; h++) {
                int r = mt * 16 + g + 8 * h;
                float2 st = stats[r];
                uint32_t* orow = g_h1pk + ((size_t)b * LL + l0 + r) * 128 + warp * 16;
#pragma unroll
                for (int nt = 0; nt < 4; nt++) {
                    float ox = (v[mt][h][nt * 2]     - st.x) * st.y * ga[nt * 2]     + be[nt * 2];
                    float oy = (v[mt][h][nt * 2 + 1] - st.x) * st.y * ga[nt * 2 + 1] + be[nt * 2 + 1];
                    orow[nt * 4 + q] = pack_h2(ox, oy);
                }
            }
    } else {
#pragma unroll
        for (int mt = 0; mt < 2; mt++)
#pragma unroll
            for (int h = 0; h < 2; h++) {
                int r = mt * 16 + g + 8 * h;
                float2 st = stats[r];
                float d = 0.f;
#pragma unroll
                for (int p = 0; p < 8; p++)
                    d += ((v[mt][h][p] - st.x) * st.y * ga[p] + be[p]) * lw[p];
                d += __shfl_xor_sync(0xffffffffu, d, 1);
                d += __shfl_xor_sync(0xffffffffu, d, 2);
                if (q == 0) dred[r * 8 + warp] = d;
            }
        __syncthreads();
        if (tid < 32) {
            float d = 0.f;
#pragma unroll
            for (int wv = 0; wv < 8; wv++) d += dred[tid * 8 + wv];
            predout[b * LL + l0 + tid] = d + __ldg(linb);
        }
    }
}

// ---------------------------------------------------------------------------
extern "C" void kernel_launch(void* const* d_in, const int* in_sizes, int n_in,
                              void* d_out, int out_size)
{
    const float* x    = (const float*)d_in[0];
    const int*   dur  = (const int*)d_in[1];
    const float* c1w  = (const float*)d_in[2];
    const float* c1b  = (const float*)d_in[3];
    const float* ln1g = (const float*)d_in[4];
    const float* ln1b = (const float*)d_in[5];
    const float* c2w  = (const float*)d_in[6];
    const float* c2b  = (const float*)d_in[7];
    const float* ln2g = (const float*)d_in[8];
    const float* ln2b = (const float*)d_in[9];
    const float* linw = (const float*)d_in[10];
    const float* linb = (const float*)d_in[11];

    float* out  = (float*)d_out;
    float* pred = out + (size_t)BB * MEL * CC;

    cudaFuncSetAttribute(conv_mma_kernel<false>,
                         cudaFuncAttributeMaxDynamicSharedMemorySize, SMEM_BYTES);
    cudaFuncSetAttribute(conv_mma_kernel<true>,
                         cudaFuncAttributeMaxDynamicSharedMemorySize, SMEM_BYTES);

    prep_kernel<<<320, 512>>>(x, c1w, c2w, dur);

    dim3 cgrid(LL / 32, BB);
    conv_mma_kernel<false><<<cgrid, 256, SMEM_BYTES>>>(x, c1b, ln1g, ln1b,
                                                       nullptr, nullptr, nullptr, out);
    conv_mma_kernel<true><<<cgrid, 256, SMEM_BYTES>>>(x, c2b, ln2g, ln2b,
                                                      linw, linb, pred, out);
}

// round 17
// speedup vs baseline: 1.1029x; 1.1029x over previous
#include <cuda_runtime.h>
#include <cuda_fp16.h>
#include <cstdint>

#define BB   16
#define LL   512
#define CC   256
#define MEL  4096

typedef unsigned long long ull;

// ---------------------------------------------------------------------------
// Scratch (__device__ globals — allocations are forbidden)
// ---------------------------------------------------------------------------
__device__ uint32_t g_h1pk[BB * LL * 128];        // h1 packed half2 [b][l][kpair]
__device__ int      g_idx[BB * MEL];              // per-frame token index
__device__ uint32_t g_wpk[2 * 3 * 128 * 256];     // weights packed half2 [conv][tap][kpair][n]

// ---------------------------------------------------------------------------
__device__ __forceinline__ uint32_t pack_h2(float a, float b) {
    __half2 h = __floats2half2_rn(a, b);
    return *reinterpret_cast<uint32_t*>(&h);
}
__device__ __forceinline__ void mma_f16(float* d, const uint32_t* a, const uint32_t* b) {
    asm volatile(
        "mma.sync.aligned.m16n8k16.row.col.f32.f16.f16.f32 "
        "{%0,%1,%2,%3}, {%4,%5,%6,%7}, {%8,%9}, {%0,%1,%2,%3};"
        : "+f"(d[0]), "+f"(d[1]), "+f"(d[2]), "+f"(d[3])
        : "r"(a[0]), "r"(a[1]), "r"(a[2]), "r"(a[3]), "r"(b[0]), "r"(b[1]));
}
__device__ __forceinline__ uint32_t smem_u32(const void* p) {
    uint32_t a;
    asm("{ .reg .u64 t; cvta.to.shared.u64 t, %1; cvt.u32.u64 %0, t; }"
        : "=r"(a) : "l"(p));
    return a;
}
#define CP_ASYNC16(dst, src) \
    asm volatile("cp.async.ca.shared.global [%0], [%1], 16;" :: "r"(dst), "l"(src))
#define CP_COMMIT() asm volatile("cp.async.commit_group;" ::: "memory")
#define CP_WAIT2()  asm volatile("cp.async.wait_group 2;" ::: "memory")
#define CP_WAIT1()  asm volatile("cp.async.wait_group 1;" ::: "memory")
#define CP_WAIT0()  asm volatile("cp.async.wait_group 0;" ::: "memory")

// smem geometry (uint32 units). M=64 tile (R11 best).
#define A_STR 132
#define B_STR 264
#define A_U32 (66 * A_STR)               // 8712
#define B32_U32 (32 * B_STR)             // 8448 (one 32-kpair chunk)
#define IDX_OFF (A_U32 + 4 * B32_U32)    // 42504
#define SMEM_BYTES ((IDX_OFF + 256) * 4) // 171040

// ---------------------------------------------------------------------------
// Prep: w-pack (blocks 0..15) + cumsum/frame-idx (blocks 16..31). 256 threads.
// Triggers PDL at entry so conv1 can start its A-pack concurrently.
// ---------------------------------------------------------------------------
__global__ void __launch_bounds__(256) prep_kernel(const float* __restrict__ w1,
                                                   const float* __restrict__ w2,
                                                   const int* __restrict__ dur)
{
    cudaTriggerProgrammaticLaunchCompletion();
    const int tid = threadIdx.x;
    if (blockIdx.x < 16) {
        int base = blockIdx.x * 256 + tid;
#pragma unroll
        for (int r = 0; r < 12; r++) {
            int id = base + r * 4096;              // 0..49151
            int n4 = id & 63;
            int kp = (id >> 6) & 127;
            int tt = id >> 13;                     // 0..5
            int tap = tt % 3, conv = tt / 3;
            const float* src = (conv ? w2 : w1) + (size_t)tap * 65536
                             + (size_t)(2 * kp) * 256 + n4 * 4;
            float4 lo = *(const float4*)(src);
            float4 hi = *(const float4*)(src + 256);
            uint4 o;
            o.x = pack_h2(lo.x, hi.x);
            o.y = pack_h2(lo.y, hi.y);
            o.z = pack_h2(lo.z, hi.z);
            o.w = pack_h2(lo.w, hi.w);
            *(uint4*)(g_wpk + ((size_t)(conv * 3 + tap) * 128 + kp) * 256 + n4 * 4) = o;
        }
        return;
    }
    // cumsum + frame->token idx (b = bid-16), 256 threads, 2 items/thread
    __shared__ int s[LL];
    __shared__ int wsum[8];
    int b = blockIdx.x - 16;
    int lane = tid & 31, wid = tid >> 5;
    int d0 = dur[b * LL + 2 * tid];
    int d1 = dur[b * LL + 2 * tid + 1];
    int v = d0 + d1;
#pragma unroll
    for (int off = 1; off < 32; off <<= 1) {
        int tmp = __shfl_up_sync(0xffffffffu, v, off);
        if (lane >= off) v += tmp;
    }
    if (lane == 31) wsum[wid] = v;
    __syncthreads();
    if (wid == 0 && lane < 8) {
        int w = wsum[lane];
#pragma unroll
        for (int off = 1; off < 8; off <<= 1) {
            int tmp = __shfl_up_sync(0xffu, w, off);
            if (lane >= off) w += tmp;
        }
        wsum[lane] = w;
    }
    __syncthreads();
    int incl = v + (wid > 0 ? wsum[wid - 1] : 0);
    s[2 * tid]     = incl - d1;
    s[2 * tid + 1] = incl;
    __syncthreads();
    int total = s[LL - 1];
#pragma unroll
    for (int r = 0; r < 16; r++) {
        int tt = tid + r * 256;
        int lo = 0, hi = LL;
        while (lo < hi) {
            int mid = (lo + hi) >> 1;
            if (s[mid] <= tt) lo = mid + 1; else hi = mid;
        }
        g_idx[b * MEL + tt] = (tt < total) ? min(lo, LL - 1) : -1;
    }
}

// ---------------------------------------------------------------------------
// Fused conv1d(K=3,SAME)+bias+ReLU+LN [+linear head if FINAL], fp16 MMA.
// CTA = [64 l x 256 f], 256 threads / 8 warps, warp tile 64x32.
// conv1: inline A-pack from x (overlaps prep via PDL), gridDepSync, stage B/idx.
// conv2: pre-stage B/idx (prep data), gridDepSync, A via direct LDG from h1.
// B pipeline: 4 buffers, 32-kpair chunks, 12 iters, ONE barrier per iter.
// Each conv streams half the regulate output; gathers issued before MMA.
// ---------------------------------------------------------------------------
template <bool FINAL>
__global__ void __launch_bounds__(256, 1)
conv_mma_kernel(const float* __restrict__ xin,
                const float* __restrict__ bias,
                const float* __restrict__ gamma,
                const float* __restrict__ beta,
                const float* __restrict__ linw,
                const float* __restrict__ linb,
                float* __restrict__ predout,
                float* __restrict__ regout)
{
    extern __shared__ __align__(16) uint32_t smu[];
    uint32_t* sA2 = smu;
    int* sIdx = (int*)(smu + IDX_OFF);
    const uint32_t sa_u32 = smem_u32(sA2);
    const uint32_t sb_base = sa_u32 + A_U32 * 4;
    const uint32_t sidx_u32 = smem_u32(sIdx);

    const int tid  = threadIdx.x;
    const int warp = tid >> 5, lane = tid & 31;
    const int g = lane >> 2, q = lane & 3;
    const int n0 = warp * 32;
    const int b  = blockIdx.y;
    const int l0 = blockIdx.x * 64;
    const int CONV = FINAL ? 1 : 0;
    const int fbase = blockIdx.x * 512 + (FINAL ? 256 : 0);

    auto stageB = [&](int ck) {
        const int buf = ck & 3;
        const uint32_t* src = g_wpk + ((size_t)(CONV * 3 + (ck >> 2)) * 128 + (ck & 3) * 32) * 256;
        const uint32_t bdst = sb_base + (uint32_t)buf * B32_U32 * 4;
#pragma unroll
        for (int i = 0; i < 8; i++) {
            int idx = tid + i * 256;               // 0..2047 16B segs
            int c = idx >> 6, n4 = idx & 63;
            CP_ASYNC16(bdst + (uint32_t)(c * B_STR + n4 * 4) * 4,
                       src + (size_t)c * 256 + n4 * 4);
        }
        CP_COMMIT();
    };

    if (!FINAL) {
        // ---- A inline pack from fp32 x: overlaps prep (PDL) ----
        const float* inb = xin + (size_t)b * LL * CC;
#pragma unroll 4
        for (int i = 0; i < 17; i++) {
            int idx = tid + i * 256;               // need 66*64 = 4224
            if (idx < 66 * 64) {
                int c4 = idx & 63, row = idx >> 6;
                int grow = l0 + row - 1;
                float4 v = make_float4(0.f, 0.f, 0.f, 0.f);
                if (grow >= 0 && grow < LL)
                    v = *(const float4*)(inb + (size_t)grow * CC + c4 * 4);
                uint32_t h01 = pack_h2(v.x, v.y);
                uint32_t h23 = pack_h2(v.z, v.w);
                *(ull*)(sA2 + row * A_STR + c4 * 2) = ((ull)h23 << 32) | h01;
            }
        }
        cudaGridDependencySynchronize();           // prep done: g_wpk/g_idx ready
        cudaTriggerProgrammaticLaunchCompletion(); // conv2 may launch (prep done)
        stageB(0);                                 // g0
        if (tid < 64)
            CP_ASYNC16(sidx_u32 + tid * 16, g_idx + b * MEL + fbase + tid * 4);
        CP_COMMIT();                               // g1
        stageB(1);                                 // g2
        stageB(2);                                 // g3
    } else {
        // conv2 launched only after conv1 triggered => prep complete
        stageB(0);                                 // g0
        if (tid < 64)
            CP_ASYNC16(sidx_u32 + tid * 16, g_idx + b * MEL + fbase + tid * 4);
        CP_COMMIT();                               // g1
        stageB(1);                                 // g2
        stageB(2);                                 // g3
        cudaGridDependencySynchronize();           // conv1 done: g_h1pk ready
        // ---- A direct LDG from packed h1 (overlaps in-flight B cp.asyncs) ----
        const uint4* apk = (const uint4*)g_h1pk + (size_t)b * LL * 32;
#pragma unroll
        for (int i = 0; i < 9; i++) {
            int idx = tid + i * 256;               // need 66*32 = 2112 segs
            if (idx < 66 * 32) {
                int row = idx >> 5, seg = idx & 31;
                int grow = l0 + row - 1;
                uint4 v = make_uint4(0u, 0u, 0u, 0u);
                if (grow >= 0 && grow < LL)
                    v = apk[(size_t)grow * 32 + seg];
                *(uint4*)(sA2 + row * A_STR + seg * 4) = v;
            }
        }
    }

    float acc[4][4][4];
#pragma unroll
    for (int mt = 0; mt < 4; mt++)
#pragma unroll
        for (int nt = 0; nt < 4; nt++)
#pragma unroll
            for (int r = 0; r < 4; r++) acc[mt][nt][r] = 0.f;

    for (int it = 0; it < 12; it++) {
        const int ktap = it >> 2, koff = (it & 3) * 32;
        if (it <= 9) CP_WAIT2();
        else if (it == 10) CP_WAIT1();
        else CP_WAIT0();
        __syncthreads();
        if (it + 3 < 12) stageB(it + 3);

        // ---- regulate: issue gathers now; latency hides under MMA ----
        int ix[6];
        float4 vv[6];
#pragma unroll
        for (int u = 0; u < 6; u++) {
            int s = it * 6 + u;
            ix[u] = (s < 64) ? sIdx[(tid + s * 256) >> 6] : -1;
        }
#pragma unroll
        for (int u = 0; u < 6; u++) {
            vv[u] = make_float4(0.f, 0.f, 0.f, 0.f);
            if (ix[u] >= 0) {
                int s = it * 6 + u;
                int c4 = (tid + s * 256) & 63;
                vv[u] = *(const float4*)(xin + ((size_t)b * LL + ix[u]) * CC + c4 * 4);
            }
        }

        const uint32_t* ab = sA2 + (ktap + g) * A_STR + koff + q;
        const uint32_t* bb = (uint32_t*)(smu + A_U32 + (it & 3) * B32_U32) + n0 + g;
#pragma unroll
        for (int ks = 0; ks < 4; ks++) {
            uint32_t af[4][4], bf[4][2];
#pragma unroll
            for (int mt = 0; mt < 4; mt++) {
                const uint32_t* ap = ab + mt * (16 * A_STR) + ks * 8;
                af[mt][0] = ap[0];
                af[mt][1] = ap[8 * A_STR];
                af[mt][2] = ap[4];
                af[mt][3] = ap[8 * A_STR + 4];
            }
#pragma unroll
            for (int nt = 0; nt < 4; nt++) {
                bf[nt][0] = bb[(ks * 8 + q) * B_STR + nt * 8];
                bf[nt][1] = bb[(ks * 8 + q + 4) * B_STR + nt * 8];
            }
#pragma unroll
            for (int mt = 0; mt < 4; mt++)
#pragma unroll
                for (int nt = 0; nt < 4; nt++)
                    mma_f16(acc[mt][nt], af[mt], bf[nt]);
        }

        // ---- regulate stores ----
#pragma unroll
        for (int u = 0; u < 6; u++) {
            int s = it * 6 + u;
            if (s < 64) {
                int j = tid + s * 256;
                int fr = j >> 6, c4 = j & 63;
                *(float4*)(regout + ((size_t)b * MEL + fbase + fr) * CC + c4 * 4) = vv[u];
            }
        }
    }
    __syncthreads();

    // ---- epilogue: bias + ReLU + LN (fused), optional linear head ----
    float bi[8], ga[8], be[8], lw[8];
#pragma unroll
    for (int nt = 0; nt < 4; nt++)
#pragma unroll
        for (int j = 0; j < 2; j++) {
            int c = n0 + nt * 8 + 2 * q + j;
            bi[nt * 2 + j] = __ldg(bias + c);
            ga[nt * 2 + j] = __ldg(gamma + c);
            be[nt * 2 + j] = __ldg(beta + c);
            if (FINAL) lw[nt * 2 + j] = __ldg(linw + c);
        }

    float v[4][2][8];
    float2* red   = (float2*)sA2;                  // [64 rows][8 warps]
    float2* stats = red + 512;                     // [64]
    float*  dred  = (float*)sA2 + 2048;            // [64 rows][8 warps]

#pragma unroll
    for (int mt = 0; mt < 4; mt++)
#pragma unroll
        for (int h = 0; h < 2; h++) {
            float s = 0.f, s2 = 0.f;
#pragma unroll
            for (int nt = 0; nt < 4; nt++)
#pragma unroll
                for (int j = 0; j < 2; j++) {
                    float x = acc[mt][nt][h * 2 + j] + bi[nt * 2 + j];
                    x = fmaxf(x, 0.f);
                    v[mt][h][nt * 2 + j] = x;
                    s += x; s2 += x * x;
                }
            s  += __shfl_xor_sync(0xffffffffu, s, 1);
            s2 += __shfl_xor_sync(0xffffffffu, s2, 1);
            s  += __shfl_xor_sync(0xffffffffu, s, 2);
            s2 += __shfl_xor_sync(0xffffffffu, s2, 2);
            if (q == 0)
                red[(mt * 16 + g + 8 * h) * 8 + warp] = make_float2(s, s2);
        }
    __syncthreads();
    if (tid < 64) {
        float s = 0.f, s2 = 0.f;
#pragma unroll
        for (int wv = 0; wv < 8; wv++) {
            float2 p = red[tid * 8 + wv];
            s += p.x; s2 += p.y;
        }
        float mu = s * (1.f / 256.f);
        float var = s2 * (1.f / 256.f) - mu * mu;
        stats[tid] = make_float2(mu, rsqrtf(var + 1e-5f));
    }
    __syncthreads();

    if (!FINAL) {
#pragma unroll
        for (int mt = 0; mt < 4; mt++)
#pragma unroll
            for (int h = 0; h < 2; h++) {
                int r = mt * 16 + g + 8 * h;
                float2 st = stats[r];
                uint32_t* orow = g_h1pk + ((size_t)b * LL + l0 + r) * 128 + warp * 16;
#pragma unroll
                for (int nt = 0; nt < 4; nt++) {
                    float ox = (v[mt][h][nt * 2]     - st.x) * st.y * ga[nt * 2]     + be[nt * 2];
                    float oy = (v[mt][h][nt * 2 + 1] - st.x) * st.y * ga[nt * 2 + 1] + be[nt * 2 + 1];
                    orow[nt * 4 + q] = pack_h2(ox, oy);
                }
            }
    } else {
#pragma unroll
        for (int mt = 0; mt < 4; mt++)
#pragma unroll
            for (int h = 0; h < 2; h++) {
                int r = mt * 16 + g + 8 * h;
                float2 st = stats[r];
                float d = 0.f;
#pragma unroll
                for (int p = 0; p < 8; p++)
                    d += ((v[mt][h][p] - st.x) * st.y * ga[p] + be[p]) * lw[p];
                d += __shfl_xor_sync(0xffffffffu, d, 1);
                d += __shfl_xor_sync(0xffffffffu, d, 2);
                if (q == 0) dred[r * 8 + warp] = d;
            }
        __syncthreads();
        if (tid < 64) {
            float d = 0.f;
#pragma unroll
            for (int wv = 0; wv < 8; wv++) d += dred[tid * 8 + wv];
            predout[b * LL + l0 + tid] = d + __ldg(linb);
        }
    }
}

// ---------------------------------------------------------------------------
extern "C" void kernel_launch(void* const* d_in, const int* in_sizes, int n_in,
                              void* d_out, int out_size)
{
    const float* x    = (const float*)d_in[0];
    const int*   dur  = (const int*)d_in[1];
    const float* c1w  = (const float*)d_in[2];
    const float* c1b  = (const float*)d_in[3];
    const float* ln1g = (const float*)d_in[4];
    const float* ln1b = (const float*)d_in[5];
    const float* c2w  = (const float*)d_in[6];
    const float* c2b  = (const float*)d_in[7];
    const float* ln2g = (const float*)d_in[8];
    const float* ln2b = (const float*)d_in[9];
    const float* linw = (const float*)d_in[10];
    const float* linb = (const float*)d_in[11];

    float* out  = (float*)d_out;
    float* pred = out + (size_t)BB * MEL * CC;

    cudaFuncSetAttribute(conv_mma_kernel<false>,
                         cudaFuncAttributeMaxDynamicSharedMemorySize, SMEM_BYTES);
    cudaFuncSetAttribute(conv_mma_kernel<true>,
                         cudaFuncAttributeMaxDynamicSharedMemorySize, SMEM_BYTES);

    prep_kernel<<<32, 256>>>(c1w, c2w, dur);

    cudaLaunchAttribute attrs[1];
    attrs[0].id = cudaLaunchAttributeProgrammaticStreamSerialization;
    attrs[0].val.programmaticStreamSerializationAllowed = 1;

    cudaLaunchConfig_t cfg = {};
    cfg.blockDim = dim3(256, 1, 1);
    cfg.gridDim  = dim3(LL / 64, BB, 1);
    cfg.dynamicSmemBytes = SMEM_BYTES;
    cfg.stream = 0;
    cfg.attrs = attrs;
    cfg.numAttrs = 1;

    cudaLaunchKernelEx(&cfg, conv_mma_kernel<false>, x, c1b, ln1g, ln1b,
                       (const float*)nullptr, (const float*)nullptr,
                       (float*)nullptr, out);
    cudaLaunchKernelEx(&cfg, conv_mma_kernel<true>, x, c2b, ln2g, ln2b,
                       linw, linb, pred, out);
}